// round 15
// baseline (speedup 1.0000x reference)
#include <cuda_runtime.h>

#define EPSV 1e-8f

// Scratch for z = beta * cosine  (B*N floats, max 128*2048 = 1 MB)
__device__ float g_z[128 * 2048];

__device__ __forceinline__ float warpSum(float v) {
#pragma unroll
    for (int o = 16; o > 0; o >>= 1) v += __shfl_xor_sync(0xffffffffu, v, o);
    return v;
}
__device__ __forceinline__ float warpMax(float v) {
#pragma unroll
    for (int o = 16; o > 0; o >>= 1) v = fmaxf(v, __shfl_xor_sync(0xffffffffu, v, o));
    return v;
}

// ============================================================================
// Kernel 1: z[b,n] = beta[b] * cos(keys[b,n,:], k[b,:])
// K = 256 fixed. Block = 256 threads (8 warps). Each block handles 128 rows
// of one batch. Warp-per-row, fully coalesced float4 loads, 4 rows batched
// per iteration for memory-level parallelism.
// ============================================================================
__global__ void __launch_bounds__(256) cos_kernel(
    const float* __restrict__ kq, const float* __restrict__ beta,
    const float* __restrict__ keys, int N)
{
    constexpr int K = 256;
    const int b    = blockIdx.y;
    const int tid  = threadIdx.x;
    const int warp = tid >> 5;
    const int lane = tid & 31;

    __shared__ float4 skq[K / 4];
    __shared__ float  sred[8];
    __shared__ float  sbc[2];

    // Load query row into smem, compute ||q||^2 (block reduce)
    float kv = kq[(size_t)b * K + tid];
    reinterpret_cast<float*>(skq)[tid] = kv;
    float sq = warpSum(kv * kv);
    if (lane == 0) sred[warp] = sq;
    __syncthreads();
    if (tid == 0) {
        float s = 0.f;
#pragma unroll
        for (int i = 0; i < 8; i++) s += sred[i];
        sbc[0] = fmaxf(sqrtf(s), EPSV);   // qn
        sbc[1] = beta[b];
    }
    __syncthreads();
    const float qn = sbc[0];
    const float bt = sbc[1];
    const float4 q0 = skq[lane * 2];
    const float4 q1 = skq[lane * 2 + 1];

    const int rowBase = blockIdx.x * 128 + warp * 16;
    const float4* kb = reinterpret_cast<const float4*>(
        keys + ((size_t)b * N + (size_t)rowBase) * K);
    float* zb = g_z + (size_t)b * N + rowBase;

#pragma unroll 1
    for (int j = 0; j < 16; j += 4) {
        // Front-batch 8 independent LDG.128 per lane (4 rows x 2 vectors)
        float4 a[4][2];
#pragma unroll
        for (int r = 0; r < 4; r++) {
            a[r][0] = kb[(size_t)(j + r) * (K / 4) + lane * 2];
            a[r][1] = kb[(size_t)(j + r) * (K / 4) + lane * 2 + 1];
        }
#pragma unroll
        for (int r = 0; r < 4; r++) {
            float4 x0 = a[r][0], x1 = a[r][1];
            float dot = x0.x * q0.x + x0.y * q0.y + x0.z * q0.z + x0.w * q0.w
                      + x1.x * q1.x + x1.y * q1.y + x1.z * q1.z + x1.w * q1.w;
            float nrm = x0.x * x0.x + x0.y * x0.y + x0.z * x0.z + x0.w * x0.w
                      + x1.x * x1.x + x1.y * x1.y + x1.z * x1.z + x1.w * x1.w;
            dot = warpSum(dot);
            nrm = warpSum(nrm);
            if (lane == 0) {
                float kn = fmaxf(sqrtf(nrm), EPSV);
                zb[j + r] = bt * dot / (kn * qn);
            }
        }
    }
}

// ============================================================================
// Kernel 2: per-batch softmax + exact top-C threshold + mask/renorm/pow/renorm
// One block per batch, 256 threads, N = 2048 -> 8 values per thread.
// Top-C value found by binary search on the monotone bit pattern of
// e = exp(z - max) (all values in (0,1], so float bits order == value order).
// ============================================================================
__global__ void __launch_bounds__(256) topk_kernel(
    const float* __restrict__ gamma_arr, const int* __restrict__ cand,
    float* __restrict__ out, int N)
{
    constexpr int VPT = 8;          // N=2048 / 256 threads
    const int b    = blockIdx.x;
    const int tid  = threadIdx.x;
    const int warp = tid >> 5;
    const int lane = tid & 31;

    __shared__ float sred[8];
    __shared__ float sbcast;
    __shared__ int   scnt[2];

    const float* zb = g_z + (size_t)b * N;
    float z[VPT];
#pragma unroll
    for (int j = 0; j < VPT; j++) z[j] = zb[tid + j * 256];

    // ---- block max ----
    float m = -INFINITY;
#pragma unroll
    for (int j = 0; j < VPT; j++) m = fmaxf(m, z[j]);
    m = warpMax(m);
    if (lane == 0) sred[warp] = m;
    if (tid == 0) { scnt[0] = 0; scnt[1] = 0; }
    __syncthreads();
    if (tid == 0) {
        float mm = sred[0];
#pragma unroll
        for (int i = 1; i < 8; i++) mm = fmaxf(mm, sred[i]);
        sbcast = mm;
    }
    __syncthreads();
    m = sbcast;

    // ---- e = exp(z - m), S = sum e ----
    float e[VPT];
    float s = 0.f;
#pragma unroll
    for (int j = 0; j < VPT; j++) { e[j] = expf(z[j] - m); s += e[j]; }
    s = warpSum(s);
    __syncthreads();                 // protect sred/sbcast reuse
    if (lane == 0) sred[warp] = s;
    __syncthreads();
    if (tid == 0) {
        float ss = 0.f;
#pragma unroll
        for (int i = 0; i < 8; i++) ss += sred[i];
        sbcast = ss;
    }
    __syncthreads();
    const float S = sbcast;

    unsigned bits[VPT];
#pragma unroll
    for (int j = 0; j < VPT; j++) bits[j] = __float_as_uint(e[j]);

    int C = 32;
    if (cand) C = __ldg(cand);

    // ---- binary search for the C-th largest e (exact, bit-level) ----
    // e in (0, 1]: bits in [0, 0x3F800000]. Invariant: count(>=lo) >= C,
    // count(>=hi) < C. Ping-pong accumulating shared counters: 1 bar/iter.
    unsigned lo = 0u, hi = 0x3F800001u;
    int base0 = 0, base1 = 0;
    int it = 0;
    while (hi - lo > 1u) {
        unsigned mid = lo + ((hi - lo) >> 1);
        int c = 0;
#pragma unroll
        for (int j = 0; j < VPT; j++) c += (bits[j] >= mid) ? 1 : 0;
        c = __reduce_add_sync(0xffffffffu, c);
        int cur = it & 1;
        if (lane == 0) atomicAdd(&scnt[cur], c);
        __syncthreads();
        int tot = scnt[cur];
        int cnt;
        if (cur) { cnt = tot - base1; base1 = tot; }
        else     { cnt = tot - base0; base0 = tot; }
        if (cnt >= C) lo = mid; else hi = mid;
        it++;
    }
    const unsigned thr = lo;

    // ---- mask, renormalize, sharpen, renormalize (mirrors reference fp32) ----
    const float g    = gamma_arr[b];
    const float invS = 1.f / S;
    float wcm[VPT];
    float s2 = 0.f;
#pragma unroll
    for (int j = 0; j < VPT; j++) {
        float wc = e[j] * invS;
        wcm[j] = (bits[j] >= thr) ? wc : wc * 1e-16f;
        s2 += wcm[j];
    }
    s2 = warpSum(s2);
    __syncthreads();
    if (lane == 0) sred[warp] = s2;
    __syncthreads();
    if (tid == 0) {
        float ss = 0.f;
#pragma unroll
        for (int i = 0; i < 8; i++) ss += sred[i];
        sbcast = ss;
    }
    __syncthreads();
    const float invS2 = 1.f / sbcast;

    float w[VPT];
    float s3 = 0.f;
#pragma unroll
    for (int j = 0; j < VPT; j++) {
        w[j] = powf(wcm[j] * invS2, g);
        s3 += w[j];
    }
    s3 = warpSum(s3);
    __syncthreads();
    if (lane == 0) sred[warp] = s3;
    __syncthreads();
    if (tid == 0) {
        float ss = 0.f;
#pragma unroll
        for (int i = 0; i < 8; i++) ss += sred[i];
        sbcast = ss;
    }
    __syncthreads();
    const float invS3 = 1.f / sbcast;

    float* ob = out + (size_t)b * N;
#pragma unroll
    for (int j = 0; j < VPT; j++) ob[tid + j * 256] = w[j] * invS3;
}

// ============================================================================
// Launch
// ============================================================================
extern "C" void kernel_launch(void* const* d_in, const int* in_sizes, int n_in,
                              void* d_out, int out_size)
{
    const float* kq    = (const float*)d_in[0];   // [B, K]
    const float* beta  = (const float*)d_in[1];   // [B, 1]
    const float* gamma = (const float*)d_in[2];   // [B, 1]
    const float* keys  = (const float*)d_in[3];   // [B, N, K]
    const int*   cand  = (n_in > 4) ? (const int*)d_in[4] : nullptr;

    const int B = in_sizes[1];                    // 128
    const int K = in_sizes[0] / B;                // 256
    const int N = in_sizes[3] / (B * K);          // 2048
    (void)K; (void)out_size;

    dim3 g1(N / 128, B);
    cos_kernel<<<g1, 256>>>(kq, beta, keys, N);
    topk_kernel<<<B, 256>>>(gamma, cand, (float*)d_out, N);
}

// round 16
// speedup vs baseline: 1.0271x; 1.0271x over previous
#include <cuda_runtime.h>

#define EPSV 1e-8f

// Scratch for z = beta * cosine  (B*N floats, max 128*2048 = 1 MB)
__device__ float g_z[128 * 2048];

__device__ __forceinline__ float warpSum(float v) {
#pragma unroll
    for (int o = 16; o > 0; o >>= 1) v += __shfl_xor_sync(0xffffffffu, v, o);
    return v;
}
__device__ __forceinline__ float warpMax(float v) {
#pragma unroll
    for (int o = 16; o > 0; o >>= 1) v = fmaxf(v, __shfl_xor_sync(0xffffffffu, v, o));
    return v;
}

// ============================================================================
// Kernel 1: z[b,n] = beta[b] * cos(keys[b,n,:], k[b,:])
// K = 256 fixed. Block = 256 threads (8 warps). Each block handles 128 rows
// of one batch. Warp-per-row, fully coalesced float4 loads, 4 rows batched
// per iteration for memory-level parallelism.
// ============================================================================
__global__ void __launch_bounds__(256) cos_kernel(
    const float* __restrict__ kq, const float* __restrict__ beta,
    const float* __restrict__ keys, int N)
{
    constexpr int K = 256;
    const int b    = blockIdx.y;
    const int tid  = threadIdx.x;
    const int warp = tid >> 5;
    const int lane = tid & 31;

    __shared__ float4 skq[K / 4];
    __shared__ float  sred[8];
    __shared__ float  sbc[2];

    // Load query row into smem, compute ||q||^2 (block reduce)
    float kv = kq[(size_t)b * K + tid];
    reinterpret_cast<float*>(skq)[tid] = kv;
    float sq = warpSum(kv * kv);
    if (lane == 0) sred[warp] = sq;
    __syncthreads();
    if (tid == 0) {
        float s = 0.f;
#pragma unroll
        for (int i = 0; i < 8; i++) s += sred[i];
        sbc[0] = fmaxf(sqrtf(s), EPSV);   // qn
        sbc[1] = beta[b];
    }
    __syncthreads();
    const float qn = sbc[0];
    const float bt = sbc[1];
    const float4 q0 = skq[lane * 2];
    const float4 q1 = skq[lane * 2 + 1];

    const int rowBase = blockIdx.x * 128 + warp * 16;
    const float4* kb = reinterpret_cast<const float4*>(
        keys + ((size_t)b * N + (size_t)rowBase) * K);
    float* zb = g_z + (size_t)b * N + rowBase;

#pragma unroll 1
    for (int j = 0; j < 16; j += 4) {
        // Front-batch 8 independent LDG.128 per lane (4 rows x 2 vectors)
        float4 a[4][2];
#pragma unroll
        for (int r = 0; r < 4; r++) {
            a[r][0] = kb[(size_t)(j + r) * (K / 4) + lane * 2];
            a[r][1] = kb[(size_t)(j + r) * (K / 4) + lane * 2 + 1];
        }
#pragma unroll
        for (int r = 0; r < 4; r++) {
            float4 x0 = a[r][0], x1 = a[r][1];
            float dot = x0.x * q0.x + x0.y * q0.y + x0.z * q0.z + x0.w * q0.w
                      + x1.x * q1.x + x1.y * q1.y + x1.z * q1.z + x1.w * q1.w;
            float nrm = x0.x * x0.x + x0.y * x0.y + x0.z * x0.z + x0.w * x0.w
                      + x1.x * x1.x + x1.y * x1.y + x1.z * x1.z + x1.w * x1.w;
            dot = warpSum(dot);
            nrm = warpSum(nrm);
            if (lane == 0) {
                float kn = fmaxf(sqrtf(nrm), EPSV);
                zb[j + r] = bt * dot / (kn * qn);
            }
        }
    }
}

// ============================================================================
// Kernel 2: per-batch softmax + exact top-C threshold + mask/renorm/pow/renorm
// One block per batch, 256 threads, N = 2048 -> 8 values per thread.
// Top-C value found by binary search on the monotone bit pattern of
// e = exp(z - max) (all values in (0,1], so float bits order == value order).
// ============================================================================
__global__ void __launch_bounds__(256) topk_kernel(
    const float* __restrict__ gamma_arr, const int* __restrict__ cand,
    float* __restrict__ out, int N)
{
    constexpr int VPT = 8;          // N=2048 / 256 threads
    const int b    = blockIdx.x;
    const int tid  = threadIdx.x;
    const int warp = tid >> 5;
    const int lane = tid & 31;

    __shared__ float sred[8];
    __shared__ float sbcast;
    __shared__ int   scnt[2];

    const float* zb = g_z + (size_t)b * N;
    float z[VPT];
#pragma unroll
    for (int j = 0; j < VPT; j++) z[j] = zb[tid + j * 256];

    // ---- block max ----
    float m = -INFINITY;
#pragma unroll
    for (int j = 0; j < VPT; j++) m = fmaxf(m, z[j]);
    m = warpMax(m);
    if (lane == 0) sred[warp] = m;
    if (tid == 0) { scnt[0] = 0; scnt[1] = 0; }
    __syncthreads();
    if (tid == 0) {
        float mm = sred[0];
#pragma unroll
        for (int i = 1; i < 8; i++) mm = fmaxf(mm, sred[i]);
        sbcast = mm;
    }
    __syncthreads();
    m = sbcast;

    // ---- e = exp(z - m), S = sum e ----
    float e[VPT];
    float s = 0.f;
#pragma unroll
    for (int j = 0; j < VPT; j++) { e[j] = expf(z[j] - m); s += e[j]; }
    s = warpSum(s);
    __syncthreads();                 // protect sred/sbcast reuse
    if (lane == 0) sred[warp] = s;
    __syncthreads();
    if (tid == 0) {
        float ss = 0.f;
#pragma unroll
        for (int i = 0; i < 8; i++) ss += sred[i];
        sbcast = ss;
    }
    __syncthreads();
    const float S = sbcast;

    unsigned bits[VPT];
#pragma unroll
    for (int j = 0; j < VPT; j++) bits[j] = __float_as_uint(e[j]);

    int C = 32;
    if (cand) C = __ldg(cand);

    // ---- binary search for the C-th largest e (exact, bit-level) ----
    // e in (0, 1]: bits in [0, 0x3F800000]. Invariant: count(>=lo) >= C,
    // count(>=hi) < C. Ping-pong accumulating shared counters: 1 bar/iter.
    unsigned lo = 0u, hi = 0x3F800001u;
    int base0 = 0, base1 = 0;
    int it = 0;
    while (hi - lo > 1u) {
        unsigned mid = lo + ((hi - lo) >> 1);
        int c = 0;
#pragma unroll
        for (int j = 0; j < VPT; j++) c += (bits[j] >= mid) ? 1 : 0;
        c = __reduce_add_sync(0xffffffffu, c);
        int cur = it & 1;
        if (lane == 0) atomicAdd(&scnt[cur], c);
        __syncthreads();
        int tot = scnt[cur];
        int cnt;
        if (cur) { cnt = tot - base1; base1 = tot; }
        else     { cnt = tot - base0; base0 = tot; }
        if (cnt >= C) lo = mid; else hi = mid;
        it++;
    }
    const unsigned thr = lo;

    // ---- mask, renormalize, sharpen, renormalize (mirrors reference fp32) ----
    const float g    = gamma_arr[b];
    const float invS = 1.f / S;
    float wcm[VPT];
    float s2 = 0.f;
#pragma unroll
    for (int j = 0; j < VPT; j++) {
        float wc = e[j] * invS;
        wcm[j] = (bits[j] >= thr) ? wc : wc * 1e-16f;
        s2 += wcm[j];
    }
    s2 = warpSum(s2);
    __syncthreads();
    if (lane == 0) sred[warp] = s2;
    __syncthreads();
    if (tid == 0) {
        float ss = 0.f;
#pragma unroll
        for (int i = 0; i < 8; i++) ss += sred[i];
        sbcast = ss;
    }
    __syncthreads();
    const float invS2 = 1.f / sbcast;

    float w[VPT];
    float s3 = 0.f;
#pragma unroll
    for (int j = 0; j < VPT; j++) {
        w[j] = powf(wcm[j] * invS2, g);
        s3 += w[j];
    }
    s3 = warpSum(s3);
    __syncthreads();
    if (lane == 0) sred[warp] = s3;
    __syncthreads();
    if (tid == 0) {
        float ss = 0.f;
#pragma unroll
        for (int i = 0; i < 8; i++) ss += sred[i];
        sbcast = ss;
    }
    __syncthreads();
    const float invS3 = 1.f / sbcast;

    float* ob = out + (size_t)b * N;
#pragma unroll
    for (int j = 0; j < VPT; j++) ob[tid + j * 256] = w[j] * invS3;
}

// ============================================================================
// Launch
// ============================================================================
extern "C" void kernel_launch(void* const* d_in, const int* in_sizes, int n_in,
                              void* d_out, int out_size)
{
    const float* kq    = (const float*)d_in[0];   // [B, K]
    const float* beta  = (const float*)d_in[1];   // [B, 1]
    const float* gamma = (const float*)d_in[2];   // [B, 1]
    const float* keys  = (const float*)d_in[3];   // [B, N, K]
    const int*   cand  = (n_in > 4) ? (const int*)d_in[4] : nullptr;

    const int B = in_sizes[1];                    // 128
    const int K = in_sizes[0] / B;                // 256
    const int N = in_sizes[3] / (B * K);          // 2048
    (void)K; (void)out_size;

    dim3 g1(N / 128, B);
    cos_kernel<<<g1, 256>>>(kq, beta, keys, N);
    topk_kernel<<<B, 256>>>(gamma, cand, (float*)d_out, N);
}

// round 17
// speedup vs baseline: 1.0277x; 1.0006x over previous
#include <cuda_runtime.h>

#define EPSV 1e-8f

// Scratch for z = beta * cosine  (B*N floats, max 128*2048 = 1 MB)
__device__ float g_z[128 * 2048];

__device__ __forceinline__ float warpSum(float v) {
#pragma unroll
    for (int o = 16; o > 0; o >>= 1) v += __shfl_xor_sync(0xffffffffu, v, o);
    return v;
}
__device__ __forceinline__ float warpMax(float v) {
#pragma unroll
    for (int o = 16; o > 0; o >>= 1) v = fmaxf(v, __shfl_xor_sync(0xffffffffu, v, o));
    return v;
}

// ============================================================================
// Kernel 1: z[b,n] = beta[b] * cos(keys[b,n,:], k[b,:])
// K = 256 fixed. Block = 256 threads (8 warps). Each block handles 128 rows
// of one batch. Warp-per-row, fully coalesced float4 loads, 4 rows batched
// per iteration for memory-level parallelism.
// ============================================================================
__global__ void __launch_bounds__(256) cos_kernel(
    const float* __restrict__ kq, const float* __restrict__ beta,
    const float* __restrict__ keys, int N)
{
    constexpr int K = 256;
    const int b    = blockIdx.y;
    const int tid  = threadIdx.x;
    const int warp = tid >> 5;
    const int lane = tid & 31;

    __shared__ float4 skq[K / 4];
    __shared__ float  sred[8];
    __shared__ float  sbc[2];

    // Load query row into smem, compute ||q||^2 (block reduce)
    float kv = kq[(size_t)b * K + tid];
    reinterpret_cast<float*>(skq)[tid] = kv;
    float sq = warpSum(kv * kv);
    if (lane == 0) sred[warp] = sq;
    __syncthreads();
    if (tid == 0) {
        float s = 0.f;
#pragma unroll
        for (int i = 0; i < 8; i++) s += sred[i];
        sbc[0] = fmaxf(sqrtf(s), EPSV);   // qn
        sbc[1] = beta[b];
    }
    __syncthreads();
    const float qn = sbc[0];
    const float bt = sbc[1];
    const float4 q0 = skq[lane * 2];
    const float4 q1 = skq[lane * 2 + 1];

    const int rowBase = blockIdx.x * 128 + warp * 16;
    const float4* kb = reinterpret_cast<const float4*>(
        keys + ((size_t)b * N + (size_t)rowBase) * K);
    float* zb = g_z + (size_t)b * N + rowBase;

#pragma unroll 1
    for (int j = 0; j < 16; j += 4) {
        // Front-batch 8 independent LDG.128 per lane (4 rows x 2 vectors)
        float4 a[4][2];
#pragma unroll
        for (int r = 0; r < 4; r++) {
            a[r][0] = kb[(size_t)(j + r) * (K / 4) + lane * 2];
            a[r][1] = kb[(size_t)(j + r) * (K / 4) + lane * 2 + 1];
        }
#pragma unroll
        for (int r = 0; r < 4; r++) {
            float4 x0 = a[r][0], x1 = a[r][1];
            float dot = x0.x * q0.x + x0.y * q0.y + x0.z * q0.z + x0.w * q0.w
                      + x1.x * q1.x + x1.y * q1.y + x1.z * q1.z + x1.w * q1.w;
            float nrm = x0.x * x0.x + x0.y * x0.y + x0.z * x0.z + x0.w * x0.w
                      + x1.x * x1.x + x1.y * x1.y + x1.z * x1.z + x1.w * x1.w;
            dot = warpSum(dot);
            nrm = warpSum(nrm);
            if (lane == 0) {
                float kn = fmaxf(sqrtf(nrm), EPSV);
                zb[j + r] = bt * dot / (kn * qn);
            }
        }
    }
}

// ============================================================================
// Kernel 2: per-batch softmax + exact top-C threshold + mask/renorm/pow/renorm
// One block per batch, 256 threads, N = 2048 -> 8 values per thread.
// Top-C value found by binary search on the monotone bit pattern of
// e = exp(z - max) (all values in (0,1], so float bits order == value order).
// ============================================================================
__global__ void __launch_bounds__(256) topk_kernel(
    const float* __restrict__ gamma_arr, const int* __restrict__ cand,
    float* __restrict__ out, int N)
{
    constexpr int VPT = 8;          // N=2048 / 256 threads
    const int b    = blockIdx.x;
    const int tid  = threadIdx.x;
    const int warp = tid >> 5;
    const int lane = tid & 31;

    __shared__ float sred[8];
    __shared__ float sbcast;
    __shared__ int   scnt[2];

    const float* zb = g_z + (size_t)b * N;
    float z[VPT];
#pragma unroll
    for (int j = 0; j < VPT; j++) z[j] = zb[tid + j * 256];

    // ---- block max ----
    float m = -INFINITY;
#pragma unroll
    for (int j = 0; j < VPT; j++) m = fmaxf(m, z[j]);
    m = warpMax(m);
    if (lane == 0) sred[warp] = m;
    if (tid == 0) { scnt[0] = 0; scnt[1] = 0; }
    __syncthreads();
    if (tid == 0) {
        float mm = sred[0];
#pragma unroll
        for (int i = 1; i < 8; i++) mm = fmaxf(mm, sred[i]);
        sbcast = mm;
    }
    __syncthreads();
    m = sbcast;

    // ---- e = exp(z - m), S = sum e ----
    float e[VPT];
    float s = 0.f;
#pragma unroll
    for (int j = 0; j < VPT; j++) { e[j] = expf(z[j] - m); s += e[j]; }
    s = warpSum(s);
    __syncthreads();                 // protect sred/sbcast reuse
    if (lane == 0) sred[warp] = s;
    __syncthreads();
    if (tid == 0) {
        float ss = 0.f;
#pragma unroll
        for (int i = 0; i < 8; i++) ss += sred[i];
        sbcast = ss;
    }
    __syncthreads();
    const float S = sbcast;

    unsigned bits[VPT];
#pragma unroll
    for (int j = 0; j < VPT; j++) bits[j] = __float_as_uint(e[j]);

    int C = 32;
    if (cand) C = __ldg(cand);

    // ---- binary search for the C-th largest e (exact, bit-level) ----
    // e in (0, 1]: bits in [0, 0x3F800000]. Invariant: count(>=lo) >= C,
    // count(>=hi) < C. Ping-pong accumulating shared counters: 1 bar/iter.
    unsigned lo = 0u, hi = 0x3F800001u;
    int base0 = 0, base1 = 0;
    int it = 0;
    while (hi - lo > 1u) {
        unsigned mid = lo + ((hi - lo) >> 1);
        int c = 0;
#pragma unroll
        for (int j = 0; j < VPT; j++) c += (bits[j] >= mid) ? 1 : 0;
        c = __reduce_add_sync(0xffffffffu, c);
        int cur = it & 1;
        if (lane == 0) atomicAdd(&scnt[cur], c);
        __syncthreads();
        int tot = scnt[cur];
        int cnt;
        if (cur) { cnt = tot - base1; base1 = tot; }
        else     { cnt = tot - base0; base0 = tot; }
        if (cnt >= C) lo = mid; else hi = mid;
        it++;
    }
    const unsigned thr = lo;

    // ---- mask, renormalize, sharpen, renormalize (mirrors reference fp32) ----
    const float g    = gamma_arr[b];
    const float invS = 1.f / S;
    float wcm[VPT];
    float s2 = 0.f;
#pragma unroll
    for (int j = 0; j < VPT; j++) {
        float wc = e[j] * invS;
        wcm[j] = (bits[j] >= thr) ? wc : wc * 1e-16f;
        s2 += wcm[j];
    }
    s2 = warpSum(s2);
    __syncthreads();
    if (lane == 0) sred[warp] = s2;
    __syncthreads();
    if (tid == 0) {
        float ss = 0.f;
#pragma unroll
        for (int i = 0; i < 8; i++) ss += sred[i];
        sbcast = ss;
    }
    __syncthreads();
    const float invS2 = 1.f / sbcast;

    float w[VPT];
    float s3 = 0.f;
#pragma unroll
    for (int j = 0; j < VPT; j++) {
        w[j] = powf(wcm[j] * invS2, g);
        s3 += w[j];
    }
    s3 = warpSum(s3);
    __syncthreads();
    if (lane == 0) sred[warp] = s3;
    __syncthreads();
    if (tid == 0) {
        float ss = 0.f;
#pragma unroll
        for (int i = 0; i < 8; i++) ss += sred[i];
        sbcast = ss;
    }
    __syncthreads();
    const float invS3 = 1.f / sbcast;

    float* ob = out + (size_t)b * N;
#pragma unroll
    for (int j = 0; j < VPT; j++) ob[tid + j * 256] = w[j] * invS3;
}

// ============================================================================
// Launch
// ============================================================================
extern "C" void kernel_launch(void* const* d_in, const int* in_sizes, int n_in,
                              void* d_out, int out_size)
{
    const float* kq    = (const float*)d_in[0];   // [B, K]
    const float* beta  = (const float*)d_in[1];   // [B, 1]
    const float* gamma = (const float*)d_in[2];   // [B, 1]
    const float* keys  = (const float*)d_in[3];   // [B, N, K]
    const int*   cand  = (n_in > 4) ? (const int*)d_in[4] : nullptr;

    const int B = in_sizes[1];                    // 128
    const int K = in_sizes[0] / B;                // 256
    const int N = in_sizes[3] / (B * K);          // 2048
    (void)K; (void)out_size;

    dim3 g1(N / 128, B);
    cos_kernel<<<g1, 256>>>(kq, beta, keys, N);
    topk_kernel<<<B, 256>>>(gamma, cand, (float*)d_out, N);
}